// round 6
// baseline (speedup 1.0000x reference)
#include <cuda_runtime.h>

// SNN recurrence: B=1024, T=1024, H=32, I=2.
// One warp per batch, one lane per hidden unit (scalar fp32 — packed f32x2
// proved a dead end on this toolchain). Bit-exact R1 arithmetic, plus:
//  - input term u_t = bg*(x0*w0 + x1*w1) software-pipelined one step ahead,
//    so the per-step LDS is never on the critical path,
//  - m = bs*s realized as FSEL(p, bs, 0)  (bit-exact),
//  - spike-count accumulation gated to the decision window (t >= 768),
//  - uniform 2 warps/SMSP (128 blocks x 256 threads).

#define TT 1024

template <bool ACC>
__device__ __forceinline__ void run32(const float2* __restrict__ buf,
                                      float& v, float& s, float& V, float& S,
                                      float& acc,
                                      float w0, float w1, float ag, float bg,
                                      float as, float bs)
{
    // u_0 (exposed LDS once per chunk only)
    float2 xv = buf[0];
    float u = __fmul_rn(bg, __fadd_rn(__fmul_rn(xv.x, w0), __fmul_rn(xv.y, w1)));

    #pragma unroll
    for (int i = 0; i < 32; ++i) {
        // Prefetch + compute next step's input term (state-independent, off-chain)
        float un = 0.0f;
        if (i < 31) {
            float2 xn = buf[i + 1];
            un = __fmul_rn(bg, __fadd_rn(__fmul_rn(xn.x, w0), __fmul_rn(xn.y, w1)));
        }

        // v = (ag*v + u) - s      (reference evaluation order, single-rounded)
        v = __fsub_rn(__fadd_rn(__fmul_rn(ag, v), u), s);
        const bool p = (v > 1.0f);
        s = p ? 1.0f : 0.0f;
        const float m = p ? bs : 0.0f;          // == bs*s bit-exactly

        // V = (as*V + m) - S
        V = __fsub_rn(__fadd_rn(__fmul_rn(as, V), m), S);
        S = (V > 1.0f) ? 1.0f : 0.0f;

        if (ACC) acc = __fadd_rn(acc, S);
        u = un;
    }
}

__global__ __launch_bounds__(256, 1)
void snn_kernel(const float* __restrict__ x,
                const float* __restrict__ Wg,     // [32,2]
                const float* __restrict__ tau_g,  // [32]
                const float* __restrict__ tau_s,  // [32]
                const float* __restrict__ Wout,   // [32]
                const float* __restrict__ bout,   // [1]
                float* __restrict__ out)          // [1024]
{
    const int lane = threadIdx.x & 31;
    const int wib  = threadIdx.x >> 5;
    const int b    = blockIdx.x * 8 + wib;

    __shared__ float2 sbuf[8][2][32];   // [warp-in-block][double buffer][step]

    const float w0 = Wg[2 * lane];
    const float w1 = Wg[2 * lane + 1];
    const float ag = 1.0f / (1.0f + expf(-tau_g[lane]));
    const float bg = 1.0f - ag;
    const float as = 1.0f / (1.0f + expf(-tau_s[lane]));
    const float bs = 1.0f - as;

    const float2* xp = reinterpret_cast<const float2*>(x) + (size_t)b * TT;

    float v = 0.0f, s = 0.0f, V = 0.0f, S = 0.0f, acc = 0.0f;

    // Prime buffer 0
    float2 nxt = xp[lane];
    sbuf[wib][0][lane] = nxt;
    __syncwarp();
    int cur = 0;

    #pragma unroll 1
    for (int chunk = 0; chunk < 24; ++chunk) {
        nxt = xp[(chunk + 1) * 32 + lane];          // prefetch next chunk (GMEM)
        run32<false>(sbuf[wib][cur], v, s, V, S, acc, w0, w1, ag, bg, as, bs);
        sbuf[wib][cur ^ 1][lane] = nxt;
        __syncwarp();
        cur ^= 1;
    }
    #pragma unroll 1
    for (int chunk = 24; chunk < 32; ++chunk) {
        if (chunk + 1 < 32) nxt = xp[(chunk + 1) * 32 + lane];
        run32<true>(sbuf[wib][cur], v, s, V, S, acc, w0, w1, ag, bg, as, bs);
        if (chunk + 1 < 32) sbuf[wib][cur ^ 1][lane] = nxt;
        __syncwarp();
        cur ^= 1;
    }

    // out[b] = sum_h acc_h * Wout[h] + bout   (same reduction tree as R1;
    // gated acc == (acc_full - base) exactly, both are exact small ints)
    float val = __fmul_rn(acc, Wout[lane]);
    #pragma unroll
    for (int off = 16; off; off >>= 1)
        val += __shfl_xor_sync(0xffffffffu, val, off);
    if (lane == 0) out[b] = val + bout[0];
}

extern "C" void kernel_launch(void* const* d_in, const int* in_sizes, int n_in,
                              void* d_out, int out_size) {
    const float* x    = (const float*)d_in[0];
    const float* Wg   = (const float*)d_in[1];
    const float* taug = (const float*)d_in[2];
    const float* taus = (const float*)d_in[3];
    const float* Wout = (const float*)d_in[4];
    const float* bout = (const float*)d_in[5];
    float* out = (float*)d_out;

    // 1024 warps, uniform 2 warps/SMSP: 128 blocks x 256 threads
    snn_kernel<<<128, 256>>>(x, Wg, taug, taus, Wout, bout, out);
}